// round 1
// baseline (speedup 1.0000x reference)
#include <cuda_runtime.h>

// Problem constants
#define B_ 4
#define S_ 2048
#define D_ 1024
#define H_ 16
#define HS_ 64
#define MTOT (B_ * S_)   // 8192

// Scratch (static device arrays — no allocation allowed)
__device__ float g_q[(size_t)B_ * H_ * S_ * HS_];
__device__ float g_k[(size_t)B_ * H_ * S_ * HS_];
__device__ float g_v[(size_t)B_ * H_ * S_ * HS_];
__device__ float g_ctx[(size_t)B_ * S_ * D_];

// ---------------------------------------------------------------------------
// Kernel 1: fused QKV projection.
// C[m, n] = x[m, :] . W[n, :]  with W = concat(Wq, Wk, Wv) rows (virtual N=3072)
// Output scattered directly into [b, h, s, hs] layout for q/k/v.
// 64x64 block tile, BK=16, 256 threads, 4x4 register tile per thread.
// ---------------------------------------------------------------------------
__global__ __launch_bounds__(256, 1) void qkv_kernel(
    const float* __restrict__ x,
    const float* __restrict__ Wq,
    const float* __restrict__ Wk,
    const float* __restrict__ Wv)
{
    __shared__ float As[16][64];   // [k][m]
    __shared__ float Bs[16][64];   // [k][n]

    const int tid = threadIdx.x;
    const int ty  = tid >> 4;      // 0..15 -> m sub-tile
    const int tx  = tid & 15;      // 0..15 -> n sub-tile
    const int m0  = blockIdx.x * 64;
    const int n0  = blockIdx.y * 64;

    // loader mapping: each thread loads one float4 of A and one of B per k-step
    const int lr = tid >> 2;            // 0..63 (row within tile)
    const int lk = (tid & 3) * 4;       // 0,4,8,12 (k offset)

    const int gn   = n0 + lr;
    const int mat  = gn >> 10;          // 0=Q, 1=K, 2=V
    const int dcol = gn & 1023;
    const float* Wsel = (mat == 0) ? Wq : ((mat == 1) ? Wk : Wv);

    const float* ap = x + (size_t)(m0 + lr) * D_ + lk;
    const float* bp = Wsel + (size_t)dcol * D_ + lk;

    float acc[4][4];
#pragma unroll
    for (int i = 0; i < 4; i++)
#pragma unroll
        for (int j = 0; j < 4; j++) acc[i][j] = 0.0f;

    for (int k0 = 0; k0 < D_; k0 += 16) {
        float4 a4 = *(const float4*)(ap + k0);
        float4 b4 = *(const float4*)(bp + k0);
        As[lk + 0][lr] = a4.x; As[lk + 1][lr] = a4.y;
        As[lk + 2][lr] = a4.z; As[lk + 3][lr] = a4.w;
        Bs[lk + 0][lr] = b4.x; Bs[lk + 1][lr] = b4.y;
        Bs[lk + 2][lr] = b4.z; Bs[lk + 3][lr] = b4.w;
        __syncthreads();
#pragma unroll
        for (int kk = 0; kk < 16; kk++) {
            float4 a = *(const float4*)&As[kk][ty * 4];
            float4 b = *(const float4*)&Bs[kk][tx * 4];
            float av[4] = {a.x, a.y, a.z, a.w};
            float bv[4] = {b.x, b.y, b.z, b.w};
#pragma unroll
            for (int i = 0; i < 4; i++)
#pragma unroll
                for (int j = 0; j < 4; j++) acc[i][j] += av[i] * bv[j];
        }
        __syncthreads();
    }

    // scatter into [b, h, s, hs] layout (4 contiguous hs per thread -> float4)
    const int n    = n0 + tx * 4;
    const int mat2 = n >> 10;
    const int d    = n & 1023;
    const int h    = d >> 6;
    const int c    = d & 63;
    float* dstbuf = (mat2 == 0) ? g_q : ((mat2 == 1) ? g_k : g_v);
#pragma unroll
    for (int i = 0; i < 4; i++) {
        const int m = m0 + ty * 4 + i;
        const int b = m >> 11;          // m / S_
        const int s = m & 2047;         // m % S_
        float4 v = make_float4(acc[i][0], acc[i][1], acc[i][2], acc[i][3]);
        *(float4*)&dstbuf[(((size_t)(b * H_ + h)) * S_ + s) * HS_ + c] = v;
    }
}

// ---------------------------------------------------------------------------
// Kernel 2: causal flash attention, fp32.
// One CTA per (bh, q-tile of 64 rows). 256 threads as 16x16 grid, each owning
// a 4x4 patch of the 64x64 score tile / output tile.
// Smem: Qs (swizzled, k-major), KP (K swizzled k-major; aliased as P after
// scores are consumed), Vs (plain). Total exactly 48 KB static.
// Swizzle: float4 column index p' = p ^ (row >> 2); compute-phase reads are
// conflict-free LDS.128.
// ---------------------------------------------------------------------------
__global__ __launch_bounds__(256, 1) void flash_kernel()
{
    __shared__ float Qs[64 * 64];
    __shared__ float KP[64 * 64];
    __shared__ float Vs[64 * 64];

    const int tid = threadIdx.x;
    const int ty  = tid >> 4;
    const int tx  = tid & 15;
    const int qt  = blockIdx.x;     // q tile 0..31
    const int bh  = blockIdx.y;     // 0..63

    const float* Qg = g_q + (size_t)bh * S_ * HS_;
    const float* Kg = g_k + (size_t)bh * S_ * HS_;
    const float* Vg = g_v + (size_t)bh * S_ * HS_;

    const float scale = 0.125f;     // 1/sqrt(64), folded into Q

    // Load + swizzle Q tile (once)
#pragma unroll
    for (int i = 0; i < 4; i++) {
        const int idx = tid + i * 256;   // float4 index 0..1023
        const int r   = idx >> 4;        // row (m) 0..63
        const int c4  = (idx & 15) * 4;  // hs base
        float4 v = *(const float4*)(Qg + (size_t)(qt * 64 + r) * HS_ + c4);
        const int p = r >> 2, ri = r & 3;
        const float vv[4] = {v.x, v.y, v.z, v.w};
#pragma unroll
        for (int j = 0; j < 4; j++) {
            const int c = c4 + j;
            Qs[c * 64 + (((p ^ (c >> 2)) << 2) | ri)] = vv[j] * scale;
        }
    }

    float o[4][4];
    float mrow[4], lrow[4];
#pragma unroll
    for (int i = 0; i < 4; i++) {
        mrow[i] = -3.0e38f; lrow[i] = 0.0f;
#pragma unroll
        for (int j = 0; j < 4; j++) o[i][j] = 0.0f;
    }

    for (int kt = 0; kt <= qt; kt++) {
        __syncthreads();   // previous iteration's readers of KP/Vs are done

        // Load K (swizzled k-major) and V (plain [key][hs])
#pragma unroll
        for (int i = 0; i < 4; i++) {
            const int idx = tid + i * 256;
            const int r   = idx >> 4;
            const int c4  = (idx & 15) * 4;
            float4 kv = *(const float4*)(Kg + (size_t)(kt * 64 + r) * HS_ + c4);
            const int p = r >> 2, ri = r & 3;
            const float kk4[4] = {kv.x, kv.y, kv.z, kv.w};
#pragma unroll
            for (int j = 0; j < 4; j++) {
                const int c = c4 + j;
                KP[c * 64 + (((p ^ (c >> 2)) << 2) | ri)] = kk4[j];
            }
            float4 vv = *(const float4*)(Vg + (size_t)(kt * 64 + r) * HS_ + c4);
            *(float4*)&Vs[r * 64 + c4] = vv;
        }
        __syncthreads();

        // S = (Q * scale) @ K^T   (64 deep over hs)
        float s[4][4];
#pragma unroll
        for (int i = 0; i < 4; i++)
#pragma unroll
            for (int j = 0; j < 4; j++) s[i][j] = 0.0f;
#pragma unroll
        for (int kk = 0; kk < 64; kk++) {
            float4 a = *(const float4*)&Qs[kk * 64 + ((ty ^ (kk >> 2)) << 2)];
            float4 b = *(const float4*)&KP[kk * 64 + ((tx ^ (kk >> 2)) << 2)];
            const float av[4] = {a.x, a.y, a.z, a.w};
            const float bv[4] = {b.x, b.y, b.z, b.w};
#pragma unroll
            for (int i = 0; i < 4; i++)
#pragma unroll
                for (int j = 0; j < 4; j++) s[i][j] += av[i] * bv[j];
        }

        // Causal mask (only the diagonal tile needs it)
        if (kt == qt) {
#pragma unroll
            for (int i = 0; i < 4; i++)
#pragma unroll
                for (int j = 0; j < 4; j++) {
                    const int mg = ty * 4 + i, ng = tx * 4 + j;
                    if (ng > mg) s[i][j] = -3.0e38f;
                }
        }

        // Online softmax update; row stats reduced across the 16 tx threads
        // that share each row (lanes 0-15 / 16-31 of a warp -> width-16 shfl).
#pragma unroll
        for (int i = 0; i < 4; i++) {
            float rm = fmaxf(fmaxf(s[i][0], s[i][1]), fmaxf(s[i][2], s[i][3]));
#pragma unroll
            for (int mk = 1; mk < 16; mk <<= 1)
                rm = fmaxf(rm, __shfl_xor_sync(0xffffffffu, rm, mk, 16));
            const float mnew = fmaxf(mrow[i], rm);
            const float corr = __expf(mrow[i] - mnew);
            float rs = 0.0f;
#pragma unroll
            for (int j = 0; j < 4; j++) {
                s[i][j] = __expf(s[i][j] - mnew);
                rs += s[i][j];
            }
#pragma unroll
            for (int mk = 1; mk < 16; mk <<= 1)
                rs += __shfl_xor_sync(0xffffffffu, rs, mk, 16);
            lrow[i] = lrow[i] * corr + rs;
            mrow[i] = mnew;
#pragma unroll
            for (int j = 0; j < 4; j++) o[i][j] *= corr;
        }

        __syncthreads();   // everyone done reading KP as K

        // Store P transposed ([key][m]) with the same swizzle: p' = ty ^ tx
#pragma unroll
        for (int j = 0; j < 4; j++) {
            const int n = tx * 4 + j;
            *(float4*)&KP[n * 64 + ((ty ^ tx) << 2)] =
                make_float4(s[0][j], s[1][j], s[2][j], s[3][j]);
        }
        __syncthreads();

        // O += P @ V
#pragma unroll
        for (int kk = 0; kk < 64; kk++) {
            float4 p = *(const float4*)&KP[kk * 64 + ((ty ^ (kk >> 2)) << 2)];
            float4 v = *(const float4*)&Vs[kk * 64 + tx * 4];
            const float pv[4] = {p.x, p.y, p.z, p.w};
            const float vv[4] = {v.x, v.y, v.z, v.w};
#pragma unroll
            for (int i = 0; i < 4; i++)
#pragma unroll
                for (int j = 0; j < 4; j++) o[i][j] += pv[i] * vv[j];
        }
    }

    // Normalize and write to ctx in [B, S, D] layout (d = h*64 + hs)
    const int b = bh >> 4, h = bh & 15;
#pragma unroll
    for (int i = 0; i < 4; i++) {
        const float inv = 1.0f / lrow[i];
        const int sg = qt * 64 + ty * 4 + i;
        float4 v = make_float4(o[i][0] * inv, o[i][1] * inv,
                               o[i][2] * inv, o[i][3] * inv);
        *(float4*)&g_ctx[((size_t)(b * S_) + sg) * D_ + h * 64 + tx * 4] = v;
    }
}

// ---------------------------------------------------------------------------
// Kernel 3: output projection  out = ctx @ Wo^T + bo
// ---------------------------------------------------------------------------
__global__ __launch_bounds__(256, 1) void outproj_kernel(
    const float* __restrict__ Wo,
    const float* __restrict__ bo,
    float* __restrict__ out)
{
    __shared__ float As[16][64];
    __shared__ float Bs[16][64];

    const int tid = threadIdx.x;
    const int ty  = tid >> 4;
    const int tx  = tid & 15;
    const int m0  = blockIdx.x * 64;
    const int n0  = blockIdx.y * 64;

    const int lr = tid >> 2;
    const int lk = (tid & 3) * 4;

    const float* ap = g_ctx + (size_t)(m0 + lr) * D_ + lk;
    const float* bp = Wo + (size_t)(n0 + lr) * D_ + lk;

    float acc[4][4];
#pragma unroll
    for (int i = 0; i < 4; i++)
#pragma unroll
        for (int j = 0; j < 4; j++) acc[i][j] = 0.0f;

    for (int k0 = 0; k0 < D_; k0 += 16) {
        float4 a4 = *(const float4*)(ap + k0);
        float4 b4 = *(const float4*)(bp + k0);
        As[lk + 0][lr] = a4.x; As[lk + 1][lr] = a4.y;
        As[lk + 2][lr] = a4.z; As[lk + 3][lr] = a4.w;
        Bs[lk + 0][lr] = b4.x; Bs[lk + 1][lr] = b4.y;
        Bs[lk + 2][lr] = b4.z; Bs[lk + 3][lr] = b4.w;
        __syncthreads();
#pragma unroll
        for (int kk = 0; kk < 16; kk++) {
            float4 a = *(const float4*)&As[kk][ty * 4];
            float4 b = *(const float4*)&Bs[kk][tx * 4];
            float av[4] = {a.x, a.y, a.z, a.w};
            float bv[4] = {b.x, b.y, b.z, b.w};
#pragma unroll
            for (int i = 0; i < 4; i++)
#pragma unroll
                for (int j = 0; j < 4; j++) acc[i][j] += av[i] * bv[j];
        }
        __syncthreads();
    }

    const int n = n0 + tx * 4;
    float4 bias = *(const float4*)(bo + n);
    const float bb[4] = {bias.x, bias.y, bias.z, bias.w};
#pragma unroll
    for (int i = 0; i < 4; i++) {
        const int m = m0 + ty * 4 + i;
        float4 v = make_float4(acc[i][0] + bb[0], acc[i][1] + bb[1],
                               acc[i][2] + bb[2], acc[i][3] + bb[3]);
        *(float4*)&out[(size_t)m * D_ + n] = v;
    }
}

// ---------------------------------------------------------------------------
// Launch
// Input order (metadata): x, Wk, Wq, Wv, Wo, bo
// ---------------------------------------------------------------------------
extern "C" void kernel_launch(void* const* d_in, const int* in_sizes, int n_in,
                              void* d_out, int out_size)
{
    const float* x  = (const float*)d_in[0];
    const float* Wk = (const float*)d_in[1];
    const float* Wq = (const float*)d_in[2];
    const float* Wv = (const float*)d_in[3];
    const float* Wo = (const float*)d_in[4];
    const float* bo = (const float*)d_in[5];
    float* out = (float*)d_out;

    dim3 g1(MTOT / 64, (3 * D_) / 64);   // 128 x 48
    qkv_kernel<<<g1, 256>>>(x, Wq, Wk, Wv);

    dim3 g2(S_ / 64, B_ * H_);           // 32 x 64
    flash_kernel<<<g2, 256>>>();

    dim3 g3(MTOT / 64, D_ / 64);         // 128 x 16
    outproj_kernel<<<g3, 256>>>(Wo, bo, out);
}

// round 3
// speedup vs baseline: 1.8945x; 1.8945x over previous
#include <cuda_runtime.h>
#include <cuda_bf16.h>
#include <stdint.h>
#include <string.h>

// Problem constants
#define B_ 4
#define S_ 2048
#define D_ 1024
#define H_ 16
#define HS_ 64
#define MTOT (B_ * S_)   // 8192

// Scratch (static device arrays — no allocation allowed)
__device__ float g_q[(size_t)B_ * H_ * S_ * HS_];
__device__ float g_k[(size_t)B_ * H_ * S_ * HS_];
__device__ float g_v[(size_t)B_ * H_ * S_ * HS_];
__device__ float g_ctx[(size_t)B_ * S_ * D_];

// ---------------------------------------------------------------------------
// Warp-level tensor-core helpers (arch-portable PTX: sm_80+, valid on sm_103)
// ---------------------------------------------------------------------------
__device__ __forceinline__ uint32_t smem_u32(const void* p) {
    uint32_t a;
    asm("{ .reg .u64 t; cvta.to.shared.u64 t, %1; cvt.u32.u64 %0, t; }"
        : "=r"(a) : "l"(p));
    return a;
}

#define LDSM_X4(R, ADDR) \
    asm volatile("ldmatrix.sync.aligned.m8n8.x4.shared.b16 {%0,%1,%2,%3}, [%4];" \
        : "=r"((R)[0]), "=r"((R)[1]), "=r"((R)[2]), "=r"((R)[3]) : "r"(ADDR))

#define MMA16816(C, A, B0, B1) \
    asm volatile("mma.sync.aligned.m16n8k16.row.col.f32.bf16.bf16.f32 " \
        "{%0,%1,%2,%3}, {%4,%5,%6,%7}, {%8,%9}, {%0,%1,%2,%3};" \
        : "+f"((C)[0]), "+f"((C)[1]), "+f"((C)[2]), "+f"((C)[3]) \
        : "r"((A)[0]), "r"((A)[1]), "r"((A)[2]), "r"((A)[3]), \
          "r"((B0)), "r"((B1)))

// Split one float4 into hi/lo bf16x4 and store (8B each)
__device__ __forceinline__ void split_store(float4 v, char* hp, char* lp) {
    __nv_bfloat162 h01 = __float22bfloat162_rn(make_float2(v.x, v.y));
    __nv_bfloat162 h23 = __float22bfloat162_rn(make_float2(v.z, v.w));
    float2 f01 = __bfloat1622float2(h01);
    float2 f23 = __bfloat1622float2(h23);
    __nv_bfloat162 l01 = __float22bfloat162_rn(make_float2(v.x - f01.x, v.y - f01.y));
    __nv_bfloat162 l23 = __float22bfloat162_rn(make_float2(v.z - f23.x, v.w - f23.y));
    uint2 hv, lv;
    memcpy(&hv.x, &h01, 4); memcpy(&hv.y, &h23, 4);
    memcpy(&lv.x, &l01, 4); memcpy(&lv.y, &l23, 4);
    *(uint2*)hp = hv;
    *(uint2*)lp = lv;
}

// ---------------------------------------------------------------------------
// Split-bf16 tensor-core GEMM:  C[m,n] = A[m,:] . Wrow[n,:]  (k-major, K=1024)
// C = Ahi*Bhi + Ahi*Blo + Alo*Bhi accumulated in fp32 (mma.sync).
// CTA 128x128, BK=32 fp32 per stage, 8 warps (2x4), warp tile 64x32.
// Smem: 4 bf16 tiles (Ah/Al/Bh/Bl) 128 rows x pitch 40 elems (80B) each,
// double buffered: 2 * 4 * 10240B = 80KB dynamic. Pitch 40 => ldmatrix reads
// and 8B stores hit distinct bank groups (stride 20 banks).
// MODE 0: A=x, B rows from concat(Wq,Wk,Wv); scatter to g_q/g_k/g_v.
// MODE 1: A=g_ctx, B rows from Wo; out = C + bo.
// ---------------------------------------------------------------------------
#define TILE_BYTES 10240       // 128 * 40 * 2
#define BUF_STRIDE 40960       // 4 tiles
#define GEMM_DYN_SMEM (2 * BUF_STRIDE)

template<int MODE>
__global__ __launch_bounds__(256, 1) void gemm_kernel(
    const float* __restrict__ Ag,
    const float* __restrict__ W0,
    const float* __restrict__ W1,
    const float* __restrict__ W2,
    const float* __restrict__ bo,
    float* __restrict__ outp)
{
    extern __shared__ char smem[];
    const int tid  = threadIdx.x;
    const int lane = tid & 31;
    const int wid  = tid >> 5;
    const int wm   = (wid >> 2) * 64;   // warp m offset in CTA tile
    const int wn   = (wid & 3) * 32;    // warp n offset
    const int m0   = blockIdx.x * 128;
    const int n0   = blockIdx.y * 128;

    const float* Aptr = (MODE == 0) ? Ag : (const float*)g_ctx;
    const float* Wsel;
    int nbase;
    if (MODE == 0) {
        const int mat = n0 >> 10;       // 128-tile never straddles a matrix
        Wsel = (mat == 0) ? W0 : ((mat == 1) ? W1 : W2);
        nbase = n0 & 1023;
    } else {
        Wsel = W0;
        nbase = n0;
    }

    float c[4][4][4];
#pragma unroll
    for (int i = 0; i < 4; i++)
#pragma unroll
        for (int j = 0; j < 4; j++)
#pragma unroll
            for (int q = 0; q < 4; q++) c[i][j][q] = 0.0f;

    const uint32_t s0 = smem_u32(smem);
    // ldmatrix per-lane byte offsets (pitch 80B)
    // A (m16k16): row = lane%16, kseg = (lane/16)*8 elems
    const uint32_t aoff = (uint32_t)((lane & 15) * 80 + (lane >> 4) * 16);
    // B (n16k16 as two n8 tiles): row = (lane&7) + ((lane>>4)&1)*8, kseg by bit3
    const uint32_t boff = (uint32_t)(((lane & 7) + ((lane >> 4) & 1) * 8) * 80
                                     + ((lane >> 3) & 1) * 16);

    // LDG prefetch registers: 4 float4 of A, 4 of B per thread per stage
    float4 ra[4], rb[4];
#pragma unroll
    for (int i = 0; i < 4; i++) {
        const int idx = tid + (i << 8);
        const int r   = idx >> 3;
        const int c4  = (idx & 7) << 2;
        ra[i] = *(const float4*)(Aptr + (size_t)(m0 + r) * 1024 + c4);
        rb[i] = *(const float4*)(Wsel + (size_t)(nbase + r) * 1024 + c4);
    }

    for (int s = 0; s < 32; s++) {
        char* base = smem + (s & 1) * BUF_STRIDE;
        // ---- STS: split fp32 -> bf16 hi/lo ----
#pragma unroll
        for (int i = 0; i < 4; i++) {
            const int idx = tid + (i << 8);
            const int r   = idx >> 3;
            const int c4  = (idx & 7) << 2;
            const int off = r * 80 + c4 * 2;
            split_store(ra[i], base + off, base + TILE_BYTES + off);
            split_store(rb[i], base + 2 * TILE_BYTES + off,
                               base + 3 * TILE_BYTES + off);
        }
        __syncthreads();

        // ---- prefetch next stage ----
        if (s < 31) {
            const int k0 = (s + 1) << 5;
#pragma unroll
            for (int i = 0; i < 4; i++) {
                const int idx = tid + (i << 8);
                const int r   = idx >> 3;
                const int c4  = (idx & 7) << 2;
                ra[i] = *(const float4*)(Aptr + (size_t)(m0 + r) * 1024 + k0 + c4);
                rb[i] = *(const float4*)(Wsel + (size_t)(nbase + r) * 1024 + k0 + c4);
            }
        }

        // ---- compute: 3 split terms, 2 k16 steps, 4x4 warp mma grid ----
        const uint32_t sb  = s0 + (uint32_t)((s & 1) * BUF_STRIDE);
        const uint32_t sAh = sb + (uint32_t)(wm * 80) + aoff;
        const uint32_t sAl = sAh + TILE_BYTES;
        const uint32_t sBh = sb + 2 * TILE_BYTES + (uint32_t)(wn * 80) + boff;
        const uint32_t sBl = sBh + TILE_BYTES;
#pragma unroll
        for (int kk = 0; kk < 2; kk++) {
            uint32_t ah[4][4], al[4][4], bh[2][4], bl[2][4];
#pragma unroll
            for (int mi = 0; mi < 4; mi++) {
                LDSM_X4(ah[mi], sAh + mi * 1280 + kk * 32);
                LDSM_X4(al[mi], sAl + mi * 1280 + kk * 32);
            }
#pragma unroll
            for (int p = 0; p < 2; p++) {
                LDSM_X4(bh[p], sBh + p * 1280 + kk * 32);
                LDSM_X4(bl[p], sBl + p * 1280 + kk * 32);
            }
#pragma unroll
            for (int mi = 0; mi < 4; mi++)
#pragma unroll
                for (int p = 0; p < 2; p++) {
                    MMA16816(c[mi][2 * p],     ah[mi], bh[p][0], bh[p][1]);
                    MMA16816(c[mi][2 * p + 1], ah[mi], bh[p][2], bh[p][3]);
                    MMA16816(c[mi][2 * p],     ah[mi], bl[p][0], bl[p][1]);
                    MMA16816(c[mi][2 * p + 1], ah[mi], bl[p][2], bl[p][3]);
                    MMA16816(c[mi][2 * p],     al[mi], bh[p][0], bh[p][1]);
                    MMA16816(c[mi][2 * p + 1], al[mi], bh[p][2], bh[p][3]);
                }
        }
        // single sync per stage: the sync above (next iteration) orders the
        // buffer reuse; see double-buffer hazard analysis.
    }

    // ---- epilogue ----
    const int mrow = lane >> 2;
    const int ncol = (lane & 3) * 2;
#pragma unroll
    for (int mi = 0; mi < 4; mi++)
#pragma unroll
        for (int nj = 0; nj < 4; nj++) {
            const int col = n0 + wn + nj * 8 + ncol;
#pragma unroll
            for (int half = 0; half < 2; half++) {
                const int m = m0 + wm + mi * 16 + mrow + half * 8;
                const float v0 = c[mi][nj][half * 2 + 0];
                const float v1 = c[mi][nj][half * 2 + 1];
                if (MODE == 0) {
                    const int mat = col >> 10;
                    const int loc = col & 1023;
                    const int h = loc >> 6, hs = loc & 63;
                    float* dst = (mat == 0) ? g_q : ((mat == 1) ? g_k : g_v);
                    const int b = m >> 11, si = m & 2047;
                    *(float2*)&dst[(((size_t)(b * 16 + h)) * 2048 + si) * 64 + hs] =
                        make_float2(v0, v1);
                } else {
                    *(float2*)&outp[(size_t)m * 1024 + col] =
                        make_float2(v0 + bo[col], v1 + bo[col + 1]);
                }
            }
        }
}

// ---------------------------------------------------------------------------
// Kernel 2: causal flash attention, fp32 (unchanged — known good).
// ---------------------------------------------------------------------------
__global__ __launch_bounds__(256, 1) void flash_kernel()
{
    __shared__ float Qs[64 * 64];
    __shared__ float KP[64 * 64];
    __shared__ float Vs[64 * 64];

    const int tid = threadIdx.x;
    const int ty  = tid >> 4;
    const int tx  = tid & 15;
    const int qt  = blockIdx.x;
    const int bh  = blockIdx.y;

    const float* Qg = g_q + (size_t)bh * S_ * HS_;
    const float* Kg = g_k + (size_t)bh * S_ * HS_;
    const float* Vg = g_v + (size_t)bh * S_ * HS_;

    const float scale = 0.125f;

#pragma unroll
    for (int i = 0; i < 4; i++) {
        const int idx = tid + i * 256;
        const int r   = idx >> 4;
        const int c4  = (idx & 15) * 4;
        float4 v = *(const float4*)(Qg + (size_t)(qt * 64 + r) * HS_ + c4);
        const int p = r >> 2, ri = r & 3;
        const float vv[4] = {v.x, v.y, v.z, v.w};
#pragma unroll
        for (int j = 0; j < 4; j++) {
            const int c = c4 + j;
            Qs[c * 64 + (((p ^ (c >> 2)) << 2) | ri)] = vv[j] * scale;
        }
    }

    float o[4][4];
    float mrow[4], lrow[4];
#pragma unroll
    for (int i = 0; i < 4; i++) {
        mrow[i] = -3.0e38f; lrow[i] = 0.0f;
#pragma unroll
        for (int j = 0; j < 4; j++) o[i][j] = 0.0f;
    }

    for (int kt = 0; kt <= qt; kt++) {
        __syncthreads();

#pragma unroll
        for (int i = 0; i < 4; i++) {
            const int idx = tid + i * 256;
            const int r   = idx >> 4;
            const int c4  = (idx & 15) * 4;
            float4 kv = *(const float4*)(Kg + (size_t)(kt * 64 + r) * HS_ + c4);
            const int p = r >> 2, ri = r & 3;
            const float kk4[4] = {kv.x, kv.y, kv.z, kv.w};
#pragma unroll
            for (int j = 0; j < 4; j++) {
                const int c = c4 + j;
                KP[c * 64 + (((p ^ (c >> 2)) << 2) | ri)] = kk4[j];
            }
            float4 vv = *(const float4*)(Vg + (size_t)(kt * 64 + r) * HS_ + c4);
            *(float4*)&Vs[r * 64 + c4] = vv;
        }
        __syncthreads();

        float s[4][4];
#pragma unroll
        for (int i = 0; i < 4; i++)
#pragma unroll
            for (int j = 0; j < 4; j++) s[i][j] = 0.0f;
#pragma unroll
        for (int kk = 0; kk < 64; kk++) {
            float4 a = *(const float4*)&Qs[kk * 64 + ((ty ^ (kk >> 2)) << 2)];
            float4 b = *(const float4*)&KP[kk * 64 + ((tx ^ (kk >> 2)) << 2)];
            const float av[4] = {a.x, a.y, a.z, a.w};
            const float bv[4] = {b.x, b.y, b.z, b.w};
#pragma unroll
            for (int i = 0; i < 4; i++)
#pragma unroll
                for (int j = 0; j < 4; j++) s[i][j] += av[i] * bv[j];
        }

        if (kt == qt) {
#pragma unroll
            for (int i = 0; i < 4; i++)
#pragma unroll
                for (int j = 0; j < 4; j++) {
                    const int mg = ty * 4 + i, ng = tx * 4 + j;
                    if (ng > mg) s[i][j] = -3.0e38f;
                }
        }

#pragma unroll
        for (int i = 0; i < 4; i++) {
            float rm = fmaxf(fmaxf(s[i][0], s[i][1]), fmaxf(s[i][2], s[i][3]));
#pragma unroll
            for (int mk = 1; mk < 16; mk <<= 1)
                rm = fmaxf(rm, __shfl_xor_sync(0xffffffffu, rm, mk, 16));
            const float mnew = fmaxf(mrow[i], rm);
            const float corr = __expf(mrow[i] - mnew);
            float rs = 0.0f;
#pragma unroll
            for (int j = 0; j < 4; j++) {
                s[i][j] = __expf(s[i][j] - mnew);
                rs += s[i][j];
            }
#pragma unroll
            for (int mk = 1; mk < 16; mk <<= 1)
                rs += __shfl_xor_sync(0xffffffffu, rs, mk, 16);
            lrow[i] = lrow[i] * corr + rs;
            mrow[i] = mnew;
#pragma unroll
            for (int j = 0; j < 4; j++) o[i][j] *= corr;
        }

        __syncthreads();

#pragma unroll
        for (int j = 0; j < 4; j++) {
            const int n = tx * 4 + j;
            *(float4*)&KP[n * 64 + ((ty ^ tx) << 2)] =
                make_float4(s[0][j], s[1][j], s[2][j], s[3][j]);
        }
        __syncthreads();

#pragma unroll
        for (int kk = 0; kk < 64; kk++) {
            float4 p = *(const float4*)&KP[kk * 64 + ((ty ^ (kk >> 2)) << 2)];
            float4 v = *(const float4*)&Vs[kk * 64 + tx * 4];
            const float pv[4] = {p.x, p.y, p.z, p.w};
            const float vv[4] = {v.x, v.y, v.z, v.w};
#pragma unroll
            for (int i = 0; i < 4; i++)
#pragma unroll
                for (int j = 0; j < 4; j++) o[i][j] += pv[i] * vv[j];
        }
    }

    const int b = bh >> 4, h = bh & 15;
#pragma unroll
    for (int i = 0; i < 4; i++) {
        const float inv = 1.0f / lrow[i];
        const int sg = qt * 64 + ty * 4 + i;
        float4 v = make_float4(o[i][0] * inv, o[i][1] * inv,
                               o[i][2] * inv, o[i][3] * inv);
        *(float4*)&g_ctx[((size_t)(b * S_) + sg) * D_ + h * 64 + tx * 4] = v;
    }
}

// ---------------------------------------------------------------------------
// Launch.  Input order (metadata): x, Wk, Wq, Wv, Wo, bo
// ---------------------------------------------------------------------------
extern "C" void kernel_launch(void* const* d_in, const int* in_sizes, int n_in,
                              void* d_out, int out_size)
{
    const float* x  = (const float*)d_in[0];
    const float* Wk = (const float*)d_in[1];
    const float* Wq = (const float*)d_in[2];
    const float* Wv = (const float*)d_in[3];
    const float* Wo = (const float*)d_in[4];
    const float* bo = (const float*)d_in[5];
    float* out = (float*)d_out;

    static bool attr_done = false;
    if (!attr_done) {
        cudaFuncSetAttribute(gemm_kernel<0>,
                             cudaFuncAttributeMaxDynamicSharedMemorySize, GEMM_DYN_SMEM);
        cudaFuncSetAttribute(gemm_kernel<1>,
                             cudaFuncAttributeMaxDynamicSharedMemorySize, GEMM_DYN_SMEM);
        attr_done = true;
    }

    // QKV projection: M=8192, virtual N = [Wq | Wk | Wv] = 3072
    dim3 g1(MTOT / 128, 3072 / 128);     // 64 x 24
    gemm_kernel<0><<<g1, 256, GEMM_DYN_SMEM>>>(x, Wq, Wk, Wv, nullptr, nullptr);

    dim3 g2(S_ / 64, B_ * H_);           // 32 x 64
    flash_kernel<<<g2, 256>>>();

    // Output projection: M=8192, N=1024 (+ bias)
    dim3 g3(MTOT / 128, 1024 / 128);     // 64 x 8
    gemm_kernel<1><<<g3, 256, GEMM_DYN_SMEM>>>(nullptr, Wo, nullptr, nullptr, bo, out);
}

// round 4
// speedup vs baseline: 3.0673x; 1.6191x over previous
#include <cuda_runtime.h>
#include <cuda_bf16.h>
#include <stdint.h>
#include <string.h>

// Problem constants
#define B_ 4
#define S_ 2048
#define D_ 1024
#define H_ 16
#define HS_ 64
#define MTOT (B_ * S_)   // 8192

// Scratch (static device arrays — no allocation allowed)
// g_q, g_k: [bh][s][hs]   g_v: TRANSPOSED [bh][hs][s]
__device__ float g_q[(size_t)B_ * H_ * S_ * HS_];
__device__ float g_k[(size_t)B_ * H_ * S_ * HS_];
__device__ float g_v[(size_t)B_ * H_ * S_ * HS_];
__device__ float g_ctx[(size_t)B_ * S_ * D_];

// ---------------------------------------------------------------------------
// Warp-level tensor-core helpers (arch-portable PTX: sm_80+, valid on sm_103)
// ---------------------------------------------------------------------------
__device__ __forceinline__ uint32_t smem_u32(const void* p) {
    uint32_t a;
    asm("{ .reg .u64 t; cvta.to.shared.u64 t, %1; cvt.u32.u64 %0, t; }"
        : "=r"(a) : "l"(p));
    return a;
}

#define LDSM_X4(R, ADDR) \
    asm volatile("ldmatrix.sync.aligned.m8n8.x4.shared.b16 {%0,%1,%2,%3}, [%4];" \
        : "=r"((R)[0]), "=r"((R)[1]), "=r"((R)[2]), "=r"((R)[3]) : "r"(ADDR))

#define MMA16816(C, A, B0, B1) \
    asm volatile("mma.sync.aligned.m16n8k16.row.col.f32.bf16.bf16.f32 " \
        "{%0,%1,%2,%3}, {%4,%5,%6,%7}, {%8,%9}, {%0,%1,%2,%3};" \
        : "+f"((C)[0]), "+f"((C)[1]), "+f"((C)[2]), "+f"((C)[3]) \
        : "r"((A)[0]), "r"((A)[1]), "r"((A)[2]), "r"((A)[3]), \
          "r"((B0)), "r"((B1)))

// Split one float4 into hi/lo bf16x4 and store (8B each)
__device__ __forceinline__ void split_store(float4 v, char* hp, char* lp) {
    __nv_bfloat162 h01 = __float22bfloat162_rn(make_float2(v.x, v.y));
    __nv_bfloat162 h23 = __float22bfloat162_rn(make_float2(v.z, v.w));
    float2 f01 = __bfloat1622float2(h01);
    float2 f23 = __bfloat1622float2(h23);
    __nv_bfloat162 l01 = __float22bfloat162_rn(make_float2(v.x - f01.x, v.y - f01.y));
    __nv_bfloat162 l23 = __float22bfloat162_rn(make_float2(v.z - f23.x, v.w - f23.y));
    uint2 hv, lv;
    memcpy(&hv.x, &h01, 4); memcpy(&hv.y, &h23, 4);
    memcpy(&lv.x, &l01, 4); memcpy(&lv.y, &l23, 4);
    *(uint2*)hp = hv;
    *(uint2*)lp = lv;
}

// Pack two floats into bf16x2 (hi) and the residual bf16x2 (lo)
__device__ __forceinline__ void pack_hl(float a, float b,
                                        uint32_t& hi, uint32_t& lo) {
    __nv_bfloat162 h = __float22bfloat162_rn(make_float2(a, b));
    float2 f = __bfloat1622float2(h);
    __nv_bfloat162 l = __float22bfloat162_rn(make_float2(a - f.x, b - f.y));
    memcpy(&hi, &h, 4);
    memcpy(&lo, &l, 4);
}

// ---------------------------------------------------------------------------
// Split-bf16 tensor-core GEMM (unchanged from R3 except V-transpose epilogue)
// ---------------------------------------------------------------------------
#define TILE_BYTES 10240       // 128 * 40 * 2
#define BUF_STRIDE 40960       // 4 tiles
#define GEMM_DYN_SMEM (2 * BUF_STRIDE)

template<int MODE>
__global__ __launch_bounds__(256, 1) void gemm_kernel(
    const float* __restrict__ Ag,
    const float* __restrict__ W0,
    const float* __restrict__ W1,
    const float* __restrict__ W2,
    const float* __restrict__ bo,
    float* __restrict__ outp)
{
    extern __shared__ char smem[];
    const int tid  = threadIdx.x;
    const int lane = tid & 31;
    const int wid  = tid >> 5;
    const int wm   = (wid >> 2) * 64;
    const int wn   = (wid & 3) * 32;
    const int m0   = blockIdx.x * 128;
    const int n0   = blockIdx.y * 128;

    const float* Aptr = (MODE == 0) ? Ag : (const float*)g_ctx;
    const float* Wsel;
    int nbase;
    if (MODE == 0) {
        const int mat = n0 >> 10;
        Wsel = (mat == 0) ? W0 : ((mat == 1) ? W1 : W2);
        nbase = n0 & 1023;
    } else {
        Wsel = W0;
        nbase = n0;
    }

    float c[4][4][4];
#pragma unroll
    for (int i = 0; i < 4; i++)
#pragma unroll
        for (int j = 0; j < 4; j++)
#pragma unroll
            for (int q = 0; q < 4; q++) c[i][j][q] = 0.0f;

    const uint32_t s0 = smem_u32(smem);
    const uint32_t aoff = (uint32_t)((lane & 15) * 80 + (lane >> 4) * 16);
    const uint32_t boff = (uint32_t)(((lane & 7) + ((lane >> 4) & 1) * 8) * 80
                                     + ((lane >> 3) & 1) * 16);

    float4 ra[4], rb[4];
#pragma unroll
    for (int i = 0; i < 4; i++) {
        const int idx = tid + (i << 8);
        const int r   = idx >> 3;
        const int c4  = (idx & 7) << 2;
        ra[i] = *(const float4*)(Aptr + (size_t)(m0 + r) * 1024 + c4);
        rb[i] = *(const float4*)(Wsel + (size_t)(nbase + r) * 1024 + c4);
    }

    for (int s = 0; s < 32; s++) {
        char* base = smem + (s & 1) * BUF_STRIDE;
#pragma unroll
        for (int i = 0; i < 4; i++) {
            const int idx = tid + (i << 8);
            const int r   = idx >> 3;
            const int c4  = (idx & 7) << 2;
            const int off = r * 80 + c4 * 2;
            split_store(ra[i], base + off, base + TILE_BYTES + off);
            split_store(rb[i], base + 2 * TILE_BYTES + off,
                               base + 3 * TILE_BYTES + off);
        }
        __syncthreads();

        if (s < 31) {
            const int k0 = (s + 1) << 5;
#pragma unroll
            for (int i = 0; i < 4; i++) {
                const int idx = tid + (i << 8);
                const int r   = idx >> 3;
                const int c4  = (idx & 7) << 2;
                ra[i] = *(const float4*)(Aptr + (size_t)(m0 + r) * 1024 + k0 + c4);
                rb[i] = *(const float4*)(Wsel + (size_t)(nbase + r) * 1024 + k0 + c4);
            }
        }

        const uint32_t sb  = s0 + (uint32_t)((s & 1) * BUF_STRIDE);
        const uint32_t sAh = sb + (uint32_t)(wm * 80) + aoff;
        const uint32_t sAl = sAh + TILE_BYTES;
        const uint32_t sBh = sb + 2 * TILE_BYTES + (uint32_t)(wn * 80) + boff;
        const uint32_t sBl = sBh + TILE_BYTES;
#pragma unroll
        for (int kk = 0; kk < 2; kk++) {
            uint32_t ah[4][4], al[4][4], bh[2][4], bl[2][4];
#pragma unroll
            for (int mi = 0; mi < 4; mi++) {
                LDSM_X4(ah[mi], sAh + mi * 1280 + kk * 32);
                LDSM_X4(al[mi], sAl + mi * 1280 + kk * 32);
            }
#pragma unroll
            for (int p = 0; p < 2; p++) {
                LDSM_X4(bh[p], sBh + p * 1280 + kk * 32);
                LDSM_X4(bl[p], sBl + p * 1280 + kk * 32);
            }
#pragma unroll
            for (int mi = 0; mi < 4; mi++)
#pragma unroll
                for (int p = 0; p < 2; p++) {
                    MMA16816(c[mi][2 * p],     ah[mi], bh[p][0], bh[p][1]);
                    MMA16816(c[mi][2 * p + 1], ah[mi], bh[p][2], bh[p][3]);
                    MMA16816(c[mi][2 * p],     ah[mi], bl[p][0], bl[p][1]);
                    MMA16816(c[mi][2 * p + 1], ah[mi], bl[p][2], bl[p][3]);
                    MMA16816(c[mi][2 * p],     al[mi], bh[p][0], bh[p][1]);
                    MMA16816(c[mi][2 * p + 1], al[mi], bh[p][2], bh[p][3]);
                }
        }
    }

    // ---- epilogue ----
    const int mrow = lane >> 2;
    const int ncol = (lane & 3) * 2;
#pragma unroll
    for (int mi = 0; mi < 4; mi++)
#pragma unroll
        for (int nj = 0; nj < 4; nj++) {
            const int col = n0 + wn + nj * 8 + ncol;
#pragma unroll
            for (int half = 0; half < 2; half++) {
                const int m = m0 + wm + mi * 16 + mrow + half * 8;
                const float v0 = c[mi][nj][half * 2 + 0];
                const float v1 = c[mi][nj][half * 2 + 1];
                if (MODE == 0) {
                    const int mat = col >> 10;
                    const int loc = col & 1023;
                    const int h = loc >> 6, hs = loc & 63;
                    const int b = m >> 11, si = m & 2047;
                    if (mat == 2) {
                        // V stored transposed: [bh][hs][s]
                        float* dstv = g_v + ((size_t)(b * 16 + h) * 64 + hs) * 2048 + si;
                        dstv[0]    = v0;
                        dstv[2048] = v1;
                    } else {
                        float* dst = (mat == 0) ? g_q : g_k;
                        *(float2*)&dst[(((size_t)(b * 16 + h)) * 2048 + si) * 64 + hs] =
                            make_float2(v0, v1);
                    }
                } else {
                    *(float2*)&outp[(size_t)m * 1024 + col] =
                        make_float2(v0 + bo[col], v1 + bo[col + 1]);
                }
            }
        }
}

// ---------------------------------------------------------------------------
// Flash attention with mma.sync split-bf16.
// CTA: 128 q-rows x one (b,h). 8 warps, warp = 16 rows. K-tiles of 64 keys.
// Smem (pitch 144B, conflict-free ldmatrix):
//   Qh/Ql 128x64 (18432B each), Kh/Kl 64x64 (9216B), VtH/VtL [hs=64][key=64].
// S = 3-term split QK^T in fp32 frags; P packed to bf16 hi/lo A-frags in regs;
// O += 3-term split P@V. Online softmax on fragments (quad shuffles).
// ---------------------------------------------------------------------------
#define FLASH_SMEM 73728

__global__ __launch_bounds__(256, 1) void flash_mma_kernel()
{
    extern __shared__ char fsm[];
    const uint32_t s0 = smem_u32(fsm);
    const uint32_t oQh = 0, oQl = 18432, oKh = 36864, oKl = 46080,
                   oVh = 55296, oVl = 64512;

    const int tid = threadIdx.x, lane = tid & 31, wid = tid >> 5;
    const int qt = blockIdx.x, bh = blockIdx.y;
    const int wm = wid * 16;

    const float* Qg  = g_q + (size_t)bh * 2048 * 64;
    const float* Kg  = g_k + (size_t)bh * 2048 * 64;
    const float* Vtg = g_v + (size_t)bh * 64 * 2048;   // [hs][s]

    // ---- load Q tile (scaled by 1/sqrt(HS)) ----
#pragma unroll
    for (int i = 0; i < 8; i++) {
        const int idx = tid + (i << 8);
        const int r = idx >> 4, c4 = (idx & 15) << 2;
        float4 v = *(const float4*)(Qg + (size_t)(qt * 128 + r) * 64 + c4);
        v.x *= 0.125f; v.y *= 0.125f; v.z *= 0.125f; v.w *= 0.125f;
        const int off = r * 144 + (c4 << 1);
        split_store(v, fsm + oQh + off, fsm + oQl + off);
    }

    float o[8][4];
#pragma unroll
    for (int i = 0; i < 8; i++)
#pragma unroll
        for (int j = 0; j < 4; j++) o[i][j] = 0.0f;
    float mrow[2] = {-1e30f, -1e30f}, lrow[2] = {0.0f, 0.0f};

    const uint32_t aoffQ = (uint32_t)(wm * 144 + (lane & 15) * 144 + (lane >> 4) * 16);
    const uint32_t boff  = (uint32_t)(((lane & 7) + ((lane >> 4) & 1) * 8) * 144
                                      + ((lane >> 3) & 1) * 16);

    const int nkt = 2 * qt + 2;
    for (int kt = 0; kt < nkt; kt++) {
        __syncthreads();
        // ---- load K tile + Vt tile (64x64 each) ----
#pragma unroll
        for (int i = 0; i < 4; i++) {
            const int idx = tid + (i << 8);
            const int r = idx >> 4, c4 = (idx & 15) << 2;
            const int off = r * 144 + (c4 << 1);
            float4 kv = *(const float4*)(Kg + (size_t)(kt * 64 + r) * 64 + c4);
            split_store(kv, fsm + oKh + off, fsm + oKl + off);
            float4 vv = *(const float4*)(Vtg + (size_t)r * 2048 + kt * 64 + c4);
            split_store(vv, fsm + oVh + off, fsm + oVl + off);
        }
        __syncthreads();

        // ---- S = Q @ K^T (3-term split) ----
        float sc[8][4];
#pragma unroll
        for (int i = 0; i < 8; i++)
#pragma unroll
            for (int j = 0; j < 4; j++) sc[i][j] = 0.0f;
#pragma unroll
        for (int kk = 0; kk < 4; kk++) {
            uint32_t ah[4], al[4];
            LDSM_X4(ah, s0 + oQh + aoffQ + kk * 32);
            LDSM_X4(al, s0 + oQl + aoffQ + kk * 32);
#pragma unroll
            for (int nt2 = 0; nt2 < 4; nt2++) {
                uint32_t bh4[4], bl4[4];
                LDSM_X4(bh4, s0 + oKh + nt2 * 2304 + boff + kk * 32);
                LDSM_X4(bl4, s0 + oKl + nt2 * 2304 + boff + kk * 32);
                MMA16816(sc[2 * nt2],     ah, bh4[0], bh4[1]);
                MMA16816(sc[2 * nt2 + 1], ah, bh4[2], bh4[3]);
                MMA16816(sc[2 * nt2],     ah, bl4[0], bl4[1]);
                MMA16816(sc[2 * nt2 + 1], ah, bl4[2], bl4[3]);
                MMA16816(sc[2 * nt2],     al, bh4[0], bh4[1]);
                MMA16816(sc[2 * nt2 + 1], al, bh4[2], bh4[3]);
            }
        }

        // ---- causal mask (only last two k-tiles can straddle diagonal) ----
        if (kt >= 2 * qt) {
            const int baser = qt * 128 + wm + (lane >> 2);
            const int baseg = kt * 64 + ((lane & 3) << 1);
#pragma unroll
            for (int nt = 0; nt < 8; nt++)
#pragma unroll
                for (int j = 0; j < 4; j++) {
                    const int row = baser + ((j >> 1) << 3);
                    const int g   = baseg + nt * 8 + (j & 1);
                    if (g > row) sc[nt][j] = -1e30f;
                }
        }

        // ---- online softmax (rows r0 = lane>>2 and r0+8) ----
#pragma unroll
        for (int hh = 0; hh < 2; hh++) {
            float rm = -1e30f;
#pragma unroll
            for (int nt = 0; nt < 8; nt++)
                rm = fmaxf(rm, fmaxf(sc[nt][2 * hh], sc[nt][2 * hh + 1]));
            rm = fmaxf(rm, __shfl_xor_sync(0xffffffffu, rm, 1));
            rm = fmaxf(rm, __shfl_xor_sync(0xffffffffu, rm, 2));
            const float mnew = fmaxf(mrow[hh], rm);
            const float corr = __expf(mrow[hh] - mnew);
            mrow[hh] = mnew;
            float rs = 0.0f;
#pragma unroll
            for (int nt = 0; nt < 8; nt++) {
                sc[nt][2 * hh]     = __expf(sc[nt][2 * hh] - mnew);
                sc[nt][2 * hh + 1] = __expf(sc[nt][2 * hh + 1] - mnew);
                rs += sc[nt][2 * hh] + sc[nt][2 * hh + 1];
            }
            rs += __shfl_xor_sync(0xffffffffu, rs, 1);
            rs += __shfl_xor_sync(0xffffffffu, rs, 2);
            lrow[hh] = lrow[hh] * corr + rs;
#pragma unroll
            for (int nt = 0; nt < 8; nt++) {
                o[nt][2 * hh]     *= corr;
                o[nt][2 * hh + 1] *= corr;
            }
        }

        // ---- O += P @ V (3-term split; P A-frags packed from sc regs) ----
#pragma unroll
        for (int t = 0; t < 4; t++) {
            uint32_t ap[4], alp[4];
            pack_hl(sc[2 * t][0],     sc[2 * t][1],     ap[0], alp[0]);
            pack_hl(sc[2 * t][2],     sc[2 * t][3],     ap[1], alp[1]);
            pack_hl(sc[2 * t + 1][0], sc[2 * t + 1][1], ap[2], alp[2]);
            pack_hl(sc[2 * t + 1][2], sc[2 * t + 1][3], ap[3], alp[3]);
#pragma unroll
            for (int nt2 = 0; nt2 < 4; nt2++) {
                uint32_t bh4[4], bl4[4];
                LDSM_X4(bh4, s0 + oVh + nt2 * 2304 + boff + t * 32);
                LDSM_X4(bl4, s0 + oVl + nt2 * 2304 + boff + t * 32);
                MMA16816(o[2 * nt2],     ap,  bh4[0], bh4[1]);
                MMA16816(o[2 * nt2 + 1], ap,  bh4[2], bh4[3]);
                MMA16816(o[2 * nt2],     ap,  bl4[0], bl4[1]);
                MMA16816(o[2 * nt2 + 1], ap,  bl4[2], bl4[3]);
                MMA16816(o[2 * nt2],     alp, bh4[0], bh4[1]);
                MMA16816(o[2 * nt2 + 1], alp, bh4[2], bh4[3]);
            }
        }
    }

    // ---- epilogue: normalize, write to g_ctx [b][s][h*64+hs] ----
    const float inv0 = 1.0f / lrow[0];
    const float inv1 = 1.0f / lrow[1];
    const int b = bh >> 4, h = bh & 15;
    const int r0 = qt * 128 + wm + (lane >> 2);
    const int c0 = h * 64 + ((lane & 3) << 1);
#pragma unroll
    for (int nt = 0; nt < 8; nt++) {
        *(float2*)&g_ctx[(size_t)(b * 2048 + r0) * 1024 + c0 + nt * 8] =
            make_float2(o[nt][0] * inv0, o[nt][1] * inv0);
        *(float2*)&g_ctx[(size_t)(b * 2048 + r0 + 8) * 1024 + c0 + nt * 8] =
            make_float2(o[nt][2] * inv1, o[nt][3] * inv1);
    }
}

// ---------------------------------------------------------------------------
// Launch.  Input order (metadata): x, Wk, Wq, Wv, Wo, bo
// ---------------------------------------------------------------------------
extern "C" void kernel_launch(void* const* d_in, const int* in_sizes, int n_in,
                              void* d_out, int out_size)
{
    const float* x  = (const float*)d_in[0];
    const float* Wk = (const float*)d_in[1];
    const float* Wq = (const float*)d_in[2];
    const float* Wv = (const float*)d_in[3];
    const float* Wo = (const float*)d_in[4];
    const float* bo = (const float*)d_in[5];
    float* out = (float*)d_out;

    static bool attr_done = false;
    if (!attr_done) {
        cudaFuncSetAttribute(gemm_kernel<0>,
                             cudaFuncAttributeMaxDynamicSharedMemorySize, GEMM_DYN_SMEM);
        cudaFuncSetAttribute(gemm_kernel<1>,
                             cudaFuncAttributeMaxDynamicSharedMemorySize, GEMM_DYN_SMEM);
        cudaFuncSetAttribute(flash_mma_kernel,
                             cudaFuncAttributeMaxDynamicSharedMemorySize, FLASH_SMEM);
        attr_done = true;
    }

    // QKV projection: M=8192, virtual N = [Wq | Wk | Wv] = 3072
    dim3 g1(MTOT / 128, 3072 / 128);     // 64 x 24
    gemm_kernel<0><<<g1, 256, GEMM_DYN_SMEM>>>(x, Wq, Wk, Wv, nullptr, nullptr);

    dim3 g2(S_ / 128, B_ * H_);          // 16 x 64
    flash_mma_kernel<<<g2, 256, FLASH_SMEM>>>();

    // Output projection: M=8192, N=1024 (+ bias)
    dim3 g3(MTOT / 128, 1024 / 128);     // 64 x 8
    gemm_kernel<1><<<g3, 256, GEMM_DYN_SMEM>>>(nullptr, Wo, nullptr, nullptr, bo, out);
}